// round 1
// baseline (speedup 1.0000x reference)
#include <cuda_runtime.h>

// ---------------------------------------------------------------------------
// WindowGrapherPyg: fused windowed KNN graph attention, one CTA per 8x8 window.
// Phase A: gather window nodes xw[64][192] into smem (fully coalesced 32B rows)
// Phase B: Gram xw@xw^T (64x64), sq = diag, top-9 KNN per node (exact fp32,
//          stable lowest-index tie-break to match jax.lax.top_k)
// Phase C: Q,K,V GEMMs (64x192 @ 192x192) into smem, register-tiled 8x6
// Phase D: per-(node,head) 9-neighbor softmax attention, written over Q buffer
// Phase E: skip GEMM fused with attn add, direct strided scatter to output
// ---------------------------------------------------------------------------

namespace {
constexpr int Bc = 2, Cc = 192, Hc = 192, Wc = 192;
constexpr int WS = 8, NN = 64, KK = 9, HEADS = 8, DH = 24;
constexpr int NWH = Hc / WS, NWW = Wc / WS;         // 24 x 24
constexpr int WB = Bc * NWH * NWW;                  // 1152 windows
constexpr int STR = 196;                            // padded row stride (floats)
constexpr int NT = 256;
constexpr int XW_FLOATS = NN * STR;                 // 12544
constexpr int WT_FLOATS = 32 * Cc;                  // 6144 (aliases Gram 64*64)
constexpr size_t SMEM_BYTES =
    (size_t)(4 * XW_FLOATS + WT_FLOATS + NN) * sizeof(float) +
    (size_t)(NN * KK) * sizeof(int);                // 227,840 B
constexpr float INV_SQRT_DH = 0.20412414523193154f; // 1/sqrt(24)
}

// 64x192 = xw(64x192) @ W(192x192) + bias, result to smem dst (stride STR).
// Thread (ty,tx): rows ty*8..ty*8+7, cols tx+32j (j=0..5) -> 48 accumulators.
__device__ __forceinline__ void gemm_to_smem(const float* __restrict__ sXW,
                                             const float* __restrict__ Wg,
                                             const float* __restrict__ bias,
                                             float* __restrict__ sWT,
                                             float* __restrict__ dst, int tid) {
  const int ty = tid >> 5, tx = tid & 31;
  float acc[8][6];
#pragma unroll
  for (int j = 0; j < 6; j++) {
    float bj = __ldg(bias + tx + 32 * j);
#pragma unroll
    for (int r = 0; r < 8; r++) acc[r][j] = bj;
  }
  for (int ko = 0; ko < Cc; ko += 32) {
    __syncthreads();  // prior consumers of sWT done
#pragma unroll
    for (int i = 0; i < 6; i++) {  // 1536 float4 = 32x192 tile
      int t = tid + NT * i;
      int kr = t / 48, cq = t - kr * 48;
      float4 v = *(const float4*)(Wg + (ko + kr) * Cc + cq * 4);
      *(float4*)(sWT + kr * Cc + cq * 4) = v;
    }
    __syncthreads();
#pragma unroll 8
    for (int k2 = 0; k2 < 32; k2++) {
      float a[8], bb[6];
#pragma unroll
      for (int r = 0; r < 8; r++) a[r] = sXW[(ty * 8 + r) * STR + ko + k2];
#pragma unroll
      for (int j = 0; j < 6; j++) bb[j] = sWT[k2 * Cc + tx + 32 * j];
#pragma unroll
      for (int r = 0; r < 8; r++)
#pragma unroll
        for (int j = 0; j < 6; j++) acc[r][j] = fmaf(a[r], bb[j], acc[r][j]);
    }
  }
#pragma unroll
  for (int r = 0; r < 8; r++)
#pragma unroll
    for (int j = 0; j < 6; j++)
      dst[(ty * 8 + r) * STR + tx + 32 * j] = acc[r][j];
  __syncthreads();
}

// skip GEMM + attn add + strided scatter to out[B,C,H,W].
// Row group ty == nh, r == nw  -> 8 contiguous floats per (c) = two float4 STG.
__device__ __forceinline__ void gemm_skip_out(const float* __restrict__ sXW,
                                              const float* __restrict__ Wg,
                                              const float* __restrict__ bias,
                                              float* __restrict__ sWT,
                                              const float* __restrict__ sAttn,
                                              float* __restrict__ out,
                                              int b, int h0, int w0, int tid) {
  const int ty = tid >> 5, tx = tid & 31;
  float acc[8][6];
#pragma unroll
  for (int j = 0; j < 6; j++) {
    float bj = __ldg(bias + tx + 32 * j);
#pragma unroll
    for (int r = 0; r < 8; r++) acc[r][j] = bj;
  }
  for (int ko = 0; ko < Cc; ko += 32) {
    __syncthreads();
#pragma unroll
    for (int i = 0; i < 6; i++) {
      int t = tid + NT * i;
      int kr = t / 48, cq = t - kr * 48;
      float4 v = *(const float4*)(Wg + (ko + kr) * Cc + cq * 4);
      *(float4*)(sWT + kr * Cc + cq * 4) = v;
    }
    __syncthreads();
#pragma unroll 8
    for (int k2 = 0; k2 < 32; k2++) {
      float a[8], bb[6];
#pragma unroll
      for (int r = 0; r < 8; r++) a[r] = sXW[(ty * 8 + r) * STR + ko + k2];
#pragma unroll
      for (int j = 0; j < 6; j++) bb[j] = sWT[k2 * Cc + tx + 32 * j];
#pragma unroll
      for (int r = 0; r < 8; r++)
#pragma unroll
        for (int j = 0; j < 6; j++) acc[r][j] = fmaf(a[r], bb[j], acc[r][j]);
    }
  }
#pragma unroll
  for (int j = 0; j < 6; j++) {
    int c = tx + 32 * j;
    float v[8];
#pragma unroll
    for (int r = 0; r < 8; r++)
      v[r] = acc[r][j] + sAttn[(ty * 8 + r) * STR + c];
    float* dst = out + ((b * Cc + c) * Hc + h0 + ty) * Wc + w0;
    *(float4*)dst = make_float4(v[0], v[1], v[2], v[3]);
    *(float4*)(dst + 4) = make_float4(v[4], v[5], v[6], v[7]);
  }
}

__global__ void __launch_bounds__(NT, 1)
wg_kernel(const float* __restrict__ x,
          const float* __restrict__ Wq, const float* __restrict__ bq,
          const float* __restrict__ Wk, const float* __restrict__ bk,
          const float* __restrict__ Wvw, const float* __restrict__ bv,
          const float* __restrict__ Wsk, const float* __restrict__ bsk,
          float* __restrict__ out) {
  extern __shared__ float sm[];
  float* sXW = sm;
  float* sQ = sXW + XW_FLOATS;
  float* sK = sQ + XW_FLOATS;
  float* sV = sK + XW_FLOATS;
  float* sWT = sV + XW_FLOATS;   // 6144 floats; first 4096 alias Gram
  float* sG = sWT;
  float* sSq = sWT + WT_FLOATS;  // 64 floats
  int* sIdx = (int*)(sSq + NN);  // 64*9 ints

  const int tid = threadIdx.x;
  const int w = blockIdx.x;
  const int b = w / (NWH * NWW);
  const int rem = w - b * (NWH * NWW);
  const int wh = rem / NWW, ww = rem - wh * NWW;
  const int h0 = wh * WS, w0 = ww * WS;

  // ---- Phase A: gather window nodes ----
#pragma unroll
  for (int i = 0; i < 6; i++) {
    int t = tid + NT * i;          // 0..1535 : (c, nh)
    int c = t >> 3, nh = t & 7;
    const float* src = x + ((b * Cc + c) * Hc + h0 + nh) * Wc + w0;
    float4 v0 = *(const float4*)src;
    float4 v1 = *(const float4*)(src + 4);
    float* d = sXW + (nh * 8) * STR + c;
    d[0 * STR] = v0.x; d[1 * STR] = v0.y; d[2 * STR] = v0.z; d[3 * STR] = v0.w;
    d[4 * STR] = v1.x; d[5 * STR] = v1.y; d[6 * STR] = v1.z; d[7 * STR] = v1.w;
  }
  __syncthreads();

  // ---- Phase B1: Gram matrix G = xw @ xw^T (64x64), 4x4 per thread ----
  {
    const int tn = tid >> 4, tm = tid & 15;
    const float* ar = sXW + tn * 4 * STR;
    const float* br = sXW + tm * 4 * STR;
    float acc[4][4] = {};
#pragma unroll 4
    for (int k = 0; k < Cc; k++) {
      float a0 = ar[0 * STR + k], a1 = ar[1 * STR + k];
      float a2 = ar[2 * STR + k], a3 = ar[3 * STR + k];
      float b0 = br[0 * STR + k], b1 = br[1 * STR + k];
      float b2 = br[2 * STR + k], b3 = br[3 * STR + k];
      acc[0][0] = fmaf(a0, b0, acc[0][0]); acc[0][1] = fmaf(a0, b1, acc[0][1]);
      acc[0][2] = fmaf(a0, b2, acc[0][2]); acc[0][3] = fmaf(a0, b3, acc[0][3]);
      acc[1][0] = fmaf(a1, b0, acc[1][0]); acc[1][1] = fmaf(a1, b1, acc[1][1]);
      acc[1][2] = fmaf(a1, b2, acc[1][2]); acc[1][3] = fmaf(a1, b3, acc[1][3]);
      acc[2][0] = fmaf(a2, b0, acc[2][0]); acc[2][1] = fmaf(a2, b1, acc[2][1]);
      acc[2][2] = fmaf(a2, b2, acc[2][2]); acc[2][3] = fmaf(a2, b3, acc[2][3]);
      acc[3][0] = fmaf(a3, b0, acc[3][0]); acc[3][1] = fmaf(a3, b1, acc[3][1]);
      acc[3][2] = fmaf(a3, b2, acc[3][2]); acc[3][3] = fmaf(a3, b3, acc[3][3]);
    }
#pragma unroll
    for (int i = 0; i < 4; i++)
#pragma unroll
      for (int j = 0; j < 4; j++)
        sG[(tn * 4 + i) * NN + tm * 4 + j] = acc[i][j];
  }
  __syncthreads();
  if (tid < NN) sSq[tid] = sG[tid * (NN + 1)];
  __syncthreads();

  // ---- Phase B2: top-9 nearest neighbors per node (stable, exact fp32) ----
  if (tid < NN) {
    const int n = tid;
    unsigned long long mask = 1ull << n;  // exclude self
    const float sqn = sSq[n];
    const float* grow = sG + n * NN;
#pragma unroll 1
    for (int kk = 0; kk < KK; kk++) {
      float best = 3.0e38f;
      int bi = 0;
#pragma unroll 4
      for (int m = 0; m < NN; m++) {
        if ((mask >> m) & 1ull) continue;
        float d = sqn + sSq[m] - 2.0f * grow[m];
        if (d < best) { best = d; bi = m; }  // strict '<' = lowest index on ties
      }
      mask |= 1ull << bi;
      sIdx[n * KK + kk] = bi;
    }
  }
  __syncthreads();

  // ---- Phase C: Q, K, V projections ----
  gemm_to_smem(sXW, Wq, bq, sWT, sQ, tid);
  gemm_to_smem(sXW, Wk, bk, sWT, sK, tid);
  gemm_to_smem(sXW, Wvw, bv, sWT, sV, tid);

  // ---- Phase D: 9-neighbor softmax attention per (node, head) ----
  for (int t = tid; t < NN * HEADS; t += NT) {
    const int n = t & (NN - 1);
    const int h = t >> 6;
    const float* qp = sQ + n * STR + h * DH;
    float q[DH];
#pragma unroll
    for (int d4 = 0; d4 < DH / 4; d4++) {
      float4 v = *(const float4*)(qp + d4 * 4);
      q[d4 * 4 + 0] = v.x; q[d4 * 4 + 1] = v.y;
      q[d4 * 4 + 2] = v.z; q[d4 * 4 + 3] = v.w;
    }
    float sc[KK];
    int nb[KK];
#pragma unroll
    for (int kk = 0; kk < KK; kk++) {
      int m = sIdx[n * KK + kk];
      nb[kk] = m;
      const float* kp = sK + m * STR + h * DH;
      float s = 0.0f;
#pragma unroll
      for (int d4 = 0; d4 < DH / 4; d4++) {
        float4 v = *(const float4*)(kp + d4 * 4);
        s = fmaf(q[d4 * 4 + 0], v.x, s);
        s = fmaf(q[d4 * 4 + 1], v.y, s);
        s = fmaf(q[d4 * 4 + 2], v.z, s);
        s = fmaf(q[d4 * 4 + 3], v.w, s);
      }
      sc[kk] = s * INV_SQRT_DH;
    }
    float mx = sc[0];
#pragma unroll
    for (int kk = 1; kk < KK; kk++) mx = fmaxf(mx, sc[kk]);
    float ssum = 0.0f;
#pragma unroll
    for (int kk = 0; kk < KK; kk++) { sc[kk] = __expf(sc[kk] - mx); ssum += sc[kk]; }
    const float inv = 1.0f / ssum;
    float o[DH] = {};
#pragma unroll
    for (int kk = 0; kk < KK; kk++) {
      float a = sc[kk] * inv;
      const float* vp = sV + nb[kk] * STR + h * DH;
#pragma unroll
      for (int d4 = 0; d4 < DH / 4; d4++) {
        float4 v = *(const float4*)(vp + d4 * 4);
        o[d4 * 4 + 0] = fmaf(a, v.x, o[d4 * 4 + 0]);
        o[d4 * 4 + 1] = fmaf(a, v.y, o[d4 * 4 + 1]);
        o[d4 * 4 + 2] = fmaf(a, v.z, o[d4 * 4 + 2]);
        o[d4 * 4 + 3] = fmaf(a, v.w, o[d4 * 4 + 3]);
      }
    }
    float* op = sQ + n * STR + h * DH;  // overwrite own q segment with attn out
#pragma unroll
    for (int d4 = 0; d4 < DH / 4; d4++)
      *(float4*)(op + d4 * 4) =
          make_float4(o[d4 * 4 + 0], o[d4 * 4 + 1], o[d4 * 4 + 2], o[d4 * 4 + 3]);
  }
  // sync inside gemm_skip_out's first iteration guards sQ reads

  // ---- Phase E: skip GEMM + attn add + scatter to [B,C,H,W] ----
  gemm_skip_out(sXW, Wsk, bsk, sWT, sQ, out, b, h0, w0, tid);
}

extern "C" void kernel_launch(void* const* d_in, const int* in_sizes, int n_in,
                              void* d_out, int out_size) {
  const float* x   = (const float*)d_in[0];
  const float* Wq  = (const float*)d_in[1];
  const float* bq  = (const float*)d_in[2];
  const float* Wk  = (const float*)d_in[3];
  const float* bk  = (const float*)d_in[4];
  const float* Wv  = (const float*)d_in[5];
  const float* bv  = (const float*)d_in[6];
  const float* Wsk = (const float*)d_in[7];
  const float* bsk = (const float*)d_in[8];
  float* out = (float*)d_out;

  cudaFuncSetAttribute(wg_kernel, cudaFuncAttributeMaxDynamicSharedMemorySize,
                       (int)SMEM_BYTES);
  wg_kernel<<<WB, NT, SMEM_BYTES>>>(x, Wq, bq, Wk, bk, Wv, bv, Wsk, bsk, out);
}

// round 2
// speedup vs baseline: 1.2723x; 1.2723x over previous
#include <cuda_runtime.h>

// ---------------------------------------------------------------------------
// WindowGrapherPyg fused kernel, R2: packed-fp32 (fma.rn.f32x2) GEMMs.
// One CTA (256 thr) per 8x8 window; xw/Q/K/V resident in smem.
//   A: gather window nodes xw[64][192]
//   B: Gram + top-9 KNN (exact fp32, stable ties)
//   C: Q,K,V GEMMs via f32x2 (8 rows x 3 col-pairs per thread, k-unroll 4,
//      register-prefetched W tiles)
//   D: 9-neighbor softmax attention (overwrites Q)
//   E: skip GEMM + attn add + strided scatter to [B,C,H,W]
// ---------------------------------------------------------------------------

typedef unsigned long long u64;

namespace {
constexpr int Bc = 2, Cc = 192, Hc = 192, Wc = 192;
constexpr int WS = 8, NN = 64, KK = 9, HEADS = 8, DH = 24;
constexpr int NWH = Hc / WS, NWW = Wc / WS;         // 24 x 24
constexpr int WB = Bc * NWH * NWW;                  // 1152 windows
constexpr int STR = 196;                            // padded row stride
constexpr int NT = 256;
constexpr int XW_FLOATS = NN * STR;                 // 12544
constexpr int WT_FLOATS = 32 * Cc;                  // 6144 (aliases Gram 64*64)
constexpr size_t SMEM_BYTES =
    (size_t)(4 * XW_FLOATS + WT_FLOATS + NN) * sizeof(float) +
    (size_t)(NN * KK) * sizeof(int);                // 227,840 B
constexpr float INV_SQRT_DH = 0.20412414523193154f;
}

__device__ __forceinline__ u64 dup2f(float a) {
  u64 r; asm("mov.b64 %0, {%1, %1};" : "=l"(r) : "f"(a)); return r;
}
__device__ __forceinline__ u64 pack2f(float x, float y) {
  u64 r; asm("mov.b64 %0, {%1, %2};" : "=l"(r) : "f"(x), "f"(y)); return r;
}
__device__ __forceinline__ void fma2(u64& d, u64 a, u64 b) {
  asm("fma.rn.f32x2 %0, %1, %2, %0;" : "+l"(d) : "l"(a), "l"(b));
}
__device__ __forceinline__ float2 unpack2(u64 v) {
  float2 o; asm("mov.b64 {%0, %1}, %2;" : "=f"(o.x), "=f"(o.y) : "l"(v));
  return o;
}

// Core: acc[8][3] (row r = ty*8+r ; col pair j -> cols 2tx+64j, 2tx+64j+1)
// = xw(64x192) @ W(192x192) + bias, via f32x2. W tiles register-prefetched.
__device__ __forceinline__ void gemm_core(const float* __restrict__ sXW,
                                          const float* __restrict__ Wg,
                                          const float* __restrict__ bias,
                                          float* __restrict__ sWT,
                                          u64 acc[8][3], int tid) {
  const int ty = tid >> 5, tx = tid & 31;
#pragma unroll
  for (int j = 0; j < 3; j++) {
    float2 b = *(const float2*)(bias + 2 * tx + 64 * j);
    u64 bp = pack2f(b.x, b.y);
#pragma unroll
    for (int r = 0; r < 8; r++) acc[r][j] = bp;
  }
  // prefetch tile 0 into registers
  float4 pf[6];
#pragma unroll
  for (int i = 0; i < 6; i++) {
    int t = tid + NT * i, kr = t / 48, cq = t - kr * 48;
    pf[i] = *(const float4*)(Wg + kr * Cc + cq * 4);
  }
  const float* arow = sXW + ty * 8 * STR;
  for (int ko = 0; ko < Cc; ko += 32) {
    __syncthreads();  // prior consumers of sWT done
#pragma unroll
    for (int i = 0; i < 6; i++) {
      int t = tid + NT * i, kr = t / 48, cq = t - kr * 48;
      *(float4*)(sWT + kr * Cc + cq * 4) = pf[i];
    }
    __syncthreads();
    if (ko + 32 < Cc) {  // prefetch next tile, overlapped with compute below
#pragma unroll
      for (int i = 0; i < 6; i++) {
        int t = tid + NT * i, kr = t / 48, cq = t - kr * 48;
        pf[i] = *(const float4*)(Wg + (ko + 32 + kr) * Cc + cq * 4);
      }
    }
#pragma unroll
    for (int kq = 0; kq < 8; kq++) {
      float4 a4[8];
#pragma unroll
      for (int r = 0; r < 8; r++)
        a4[r] = *(const float4*)(arow + r * STR + ko + kq * 4);
#pragma unroll
      for (int kk = 0; kk < 4; kk++) {
        u64 b2[3];
#pragma unroll
        for (int j = 0; j < 3; j++)
          b2[j] = *(const u64*)(sWT + (kq * 4 + kk) * Cc + 2 * tx + 64 * j);
#pragma unroll
        for (int r = 0; r < 8; r++) {
          float av = (kk == 0) ? a4[r].x : (kk == 1) ? a4[r].y
                    : (kk == 2) ? a4[r].z : a4[r].w;
          u64 a2 = dup2f(av);
#pragma unroll
          for (int j = 0; j < 3; j++) fma2(acc[r][j], a2, b2[j]);
        }
      }
    }
  }
}

__device__ __forceinline__ void gemm_to_smem(const float* __restrict__ sXW,
                                             const float* __restrict__ Wg,
                                             const float* __restrict__ bias,
                                             float* __restrict__ sWT,
                                             float* __restrict__ dst, int tid) {
  u64 acc[8][3];
  gemm_core(sXW, Wg, bias, sWT, acc, tid);
  const int ty = tid >> 5, tx = tid & 31;
#pragma unroll
  for (int r = 0; r < 8; r++)
#pragma unroll
    for (int j = 0; j < 3; j++) {
      float2 v = unpack2(acc[r][j]);
      float* p = dst + (ty * 8 + r) * STR + 2 * tx + 64 * j;
      p[0] = v.x; p[1] = v.y;
    }
  __syncthreads();
}

__device__ __forceinline__ void gemm_skip_out(const float* __restrict__ sXW,
                                              const float* __restrict__ Wg,
                                              const float* __restrict__ bias,
                                              float* __restrict__ sWT,
                                              const float* __restrict__ sAttn,
                                              float* __restrict__ out,
                                              int b, int h0, int w0, int tid) {
  u64 acc[8][3];
  gemm_core(sXW, Wg, bias, sWT, acc, tid);
  const int ty = tid >> 5, tx = tid & 31;
#pragma unroll
  for (int j = 0; j < 3; j++) {
    const int c = 2 * tx + 64 * j;
    float vlo[8], vhi[8];
#pragma unroll
    for (int r = 0; r < 8; r++) {
      float2 v = unpack2(acc[r][j]);
      vlo[r] = v.x + sAttn[(ty * 8 + r) * STR + c];
      vhi[r] = v.y + sAttn[(ty * 8 + r) * STR + c + 1];
    }
    float* d0 = out + ((b * Cc + c) * Hc + h0 + ty) * Wc + w0;
    *(float4*)d0 = make_float4(vlo[0], vlo[1], vlo[2], vlo[3]);
    *(float4*)(d0 + 4) = make_float4(vlo[4], vlo[5], vlo[6], vlo[7]);
    float* d1 = out + ((b * Cc + c + 1) * Hc + h0 + ty) * Wc + w0;
    *(float4*)d1 = make_float4(vhi[0], vhi[1], vhi[2], vhi[3]);
    *(float4*)(d1 + 4) = make_float4(vhi[4], vhi[5], vhi[6], vhi[7]);
  }
}

__global__ void __launch_bounds__(NT, 1)
wg_kernel(const float* __restrict__ x,
          const float* __restrict__ Wq, const float* __restrict__ bq,
          const float* __restrict__ Wk, const float* __restrict__ bk,
          const float* __restrict__ Wvw, const float* __restrict__ bv,
          const float* __restrict__ Wsk, const float* __restrict__ bsk,
          float* __restrict__ out) {
  extern __shared__ float sm[];
  float* sXW = sm;
  float* sQ = sXW + XW_FLOATS;
  float* sK = sQ + XW_FLOATS;
  float* sV = sK + XW_FLOATS;
  float* sWT = sV + XW_FLOATS;   // 6144 floats; first 4096 alias Gram
  float* sG = sWT;
  float* sSq = sWT + WT_FLOATS;  // 64 floats
  int* sIdx = (int*)(sSq + NN);  // 64*9 ints

  const int tid = threadIdx.x;
  const int w = blockIdx.x;
  const int b = w / (NWH * NWW);
  const int rem = w - b * (NWH * NWW);
  const int wh = rem / NWW, ww = rem - wh * NWW;
  const int h0 = wh * WS, w0 = ww * WS;

  // ---- Phase A: gather window nodes ----
#pragma unroll
  for (int i = 0; i < 6; i++) {
    int t = tid + NT * i;          // 0..1535 : (c, nh)
    int c = t >> 3, nh = t & 7;
    const float* src = x + ((b * Cc + c) * Hc + h0 + nh) * Wc + w0;
    float4 v0 = *(const float4*)src;
    float4 v1 = *(const float4*)(src + 4);
    float* d = sXW + (nh * 8) * STR + c;
    d[0 * STR] = v0.x; d[1 * STR] = v0.y; d[2 * STR] = v0.z; d[3 * STR] = v0.w;
    d[4 * STR] = v1.x; d[5 * STR] = v1.y; d[6 * STR] = v1.z; d[7 * STR] = v1.w;
  }
  __syncthreads();

  // ---- Phase B1: Gram matrix G = xw @ xw^T (64x64), 4x4 per thread ----
  {
    const int tn = tid >> 4, tm = tid & 15;
    const float* ar = sXW + tn * 4 * STR;
    const float* br = sXW + tm * 4 * STR;
    float acc[4][4] = {};
#pragma unroll 4
    for (int k = 0; k < Cc; k++) {
      float a0 = ar[0 * STR + k], a1 = ar[1 * STR + k];
      float a2 = ar[2 * STR + k], a3 = ar[3 * STR + k];
      float b0 = br[0 * STR + k], b1 = br[1 * STR + k];
      float b2 = br[2 * STR + k], b3 = br[3 * STR + k];
      acc[0][0] = fmaf(a0, b0, acc[0][0]); acc[0][1] = fmaf(a0, b1, acc[0][1]);
      acc[0][2] = fmaf(a0, b2, acc[0][2]); acc[0][3] = fmaf(a0, b3, acc[0][3]);
      acc[1][0] = fmaf(a1, b0, acc[1][0]); acc[1][1] = fmaf(a1, b1, acc[1][1]);
      acc[1][2] = fmaf(a1, b2, acc[1][2]); acc[1][3] = fmaf(a1, b3, acc[1][3]);
      acc[2][0] = fmaf(a2, b0, acc[2][0]); acc[2][1] = fmaf(a2, b1, acc[2][1]);
      acc[2][2] = fmaf(a2, b2, acc[2][2]); acc[2][3] = fmaf(a2, b3, acc[2][3]);
      acc[3][0] = fmaf(a3, b0, acc[3][0]); acc[3][1] = fmaf(a3, b1, acc[3][1]);
      acc[3][2] = fmaf(a3, b2, acc[3][2]); acc[3][3] = fmaf(a3, b3, acc[3][3]);
    }
#pragma unroll
    for (int i = 0; i < 4; i++)
#pragma unroll
      for (int j = 0; j < 4; j++)
        sG[(tn * 4 + i) * NN + tm * 4 + j] = acc[i][j];
  }
  __syncthreads();
  if (tid < NN) sSq[tid] = sG[tid * (NN + 1)];
  __syncthreads();

  // ---- Phase B2: top-9 nearest neighbors per node (stable, exact fp32) ----
  if (tid < NN) {
    const int n = tid;
    unsigned long long mask = 1ull << n;  // exclude self
    const float sqn = sSq[n];
    const float* grow = sG + n * NN;
#pragma unroll 1
    for (int kk = 0; kk < KK; kk++) {
      float best = 3.0e38f;
      int bi = 0;
#pragma unroll 4
      for (int m = 0; m < NN; m++) {
        float d = sqn + sSq[m] - 2.0f * grow[m];
        if ((mask >> m) & 1ull) d = 3.9e38f;
        if (d < best) { best = d; bi = m; }  // strict '<' = lowest index wins
      }
      mask |= 1ull << bi;
      sIdx[n * KK + kk] = bi;
    }
  }
  __syncthreads();

  // ---- Phase C: Q, K, V projections (f32x2) ----
  gemm_to_smem(sXW, Wq, bq, sWT, sQ, tid);
  gemm_to_smem(sXW, Wk, bk, sWT, sK, tid);
  gemm_to_smem(sXW, Wvw, bv, sWT, sV, tid);

  // ---- Phase D: 9-neighbor softmax attention per (node, head) ----
  for (int t = tid; t < NN * HEADS; t += NT) {
    const int n = t & (NN - 1);
    const int h = t >> 6;
    const float* qp = sQ + n * STR + h * DH;
    float q[DH];
#pragma unroll
    for (int d4 = 0; d4 < DH / 4; d4++) {
      float4 v = *(const float4*)(qp + d4 * 4);
      q[d4 * 4 + 0] = v.x; q[d4 * 4 + 1] = v.y;
      q[d4 * 4 + 2] = v.z; q[d4 * 4 + 3] = v.w;
    }
    float sc[KK];
    int nb[KK];
#pragma unroll
    for (int kk = 0; kk < KK; kk++) {
      int m = sIdx[n * KK + kk];
      nb[kk] = m;
      const float* kp = sK + m * STR + h * DH;
      float s = 0.0f;
#pragma unroll
      for (int d4 = 0; d4 < DH / 4; d4++) {
        float4 v = *(const float4*)(kp + d4 * 4);
        s = fmaf(q[d4 * 4 + 0], v.x, s);
        s = fmaf(q[d4 * 4 + 1], v.y, s);
        s = fmaf(q[d4 * 4 + 2], v.z, s);
        s = fmaf(q[d4 * 4 + 3], v.w, s);
      }
      sc[kk] = s * INV_SQRT_DH;
    }
    float mx = sc[0];
#pragma unroll
    for (int kk = 1; kk < KK; kk++) mx = fmaxf(mx, sc[kk]);
    float ssum = 0.0f;
#pragma unroll
    for (int kk = 0; kk < KK; kk++) { sc[kk] = __expf(sc[kk] - mx); ssum += sc[kk]; }
    const float inv = 1.0f / ssum;
    float o[DH] = {};
#pragma unroll
    for (int kk = 0; kk < KK; kk++) {
      float a = sc[kk] * inv;
      const float* vp = sV + nb[kk] * STR + h * DH;
#pragma unroll
      for (int d4 = 0; d4 < DH / 4; d4++) {
        float4 v = *(const float4*)(vp + d4 * 4);
        o[d4 * 4 + 0] = fmaf(a, v.x, o[d4 * 4 + 0]);
        o[d4 * 4 + 1] = fmaf(a, v.y, o[d4 * 4 + 1]);
        o[d4 * 4 + 2] = fmaf(a, v.z, o[d4 * 4 + 2]);
        o[d4 * 4 + 3] = fmaf(a, v.w, o[d4 * 4 + 3]);
      }
    }
    float* op = sQ + n * STR + h * DH;  // overwrite own q segment with attn out
#pragma unroll
    for (int d4 = 0; d4 < DH / 4; d4++)
      *(float4*)(op + d4 * 4) =
          make_float4(o[d4 * 4 + 0], o[d4 * 4 + 1], o[d4 * 4 + 2], o[d4 * 4 + 3]);
  }
  // first __syncthreads inside gemm_skip_out's tile loop guards sQ reads

  // ---- Phase E: skip GEMM + attn add + scatter to [B,C,H,W] ----
  gemm_skip_out(sXW, Wsk, bsk, sWT, sQ, out, b, h0, w0, tid);
}

extern "C" void kernel_launch(void* const* d_in, const int* in_sizes, int n_in,
                              void* d_out, int out_size) {
  const float* x   = (const float*)d_in[0];
  const float* Wq  = (const float*)d_in[1];
  const float* bq  = (const float*)d_in[2];
  const float* Wk  = (const float*)d_in[3];
  const float* bk  = (const float*)d_in[4];
  const float* Wv  = (const float*)d_in[5];
  const float* bv  = (const float*)d_in[6];
  const float* Wsk = (const float*)d_in[7];
  const float* bsk = (const float*)d_in[8];
  float* out = (float*)d_out;

  cudaFuncSetAttribute(wg_kernel, cudaFuncAttributeMaxDynamicSharedMemorySize,
                       (int)SMEM_BYTES);
  wg_kernel<<<WB, NT, SMEM_BYTES>>>(x, Wq, bq, Wk, bk, Wv, bv, Wsk, bsk, out);
}

// round 3
// speedup vs baseline: 1.3023x; 1.0236x over previous
#include <cuda_runtime.h>

// ---------------------------------------------------------------------------
// WindowGrapherPyg fused kernel, R3: 512 threads/CTA + conflict-free Gram.
// One CTA per 8x8 window; xw/Q/K/V resident in smem; f32x2 packed GEMMs.
// ---------------------------------------------------------------------------

typedef unsigned long long u64;

namespace {
constexpr int Bc = 2, Cc = 192, Hc = 192, Wc = 192;
constexpr int WS = 8, NN = 64, KK = 9, HEADS = 8, DH = 24;
constexpr int NWH = Hc / WS, NWW = Wc / WS;         // 24 x 24
constexpr int WB = Bc * NWH * NWW;                  // 1152 windows
constexpr int STR = 196;                            // padded row stride
constexpr int NT = 512;
constexpr int XW_FLOATS = NN * STR;                 // 12544
constexpr int WT_FLOATS = 32 * Cc;                  // 6144 (aliases Gram 64*64)
constexpr size_t SMEM_BYTES =
    (size_t)(4 * XW_FLOATS + WT_FLOATS + NN) * sizeof(float) +
    (size_t)(NN * KK) * sizeof(int);                // 227,840 B
constexpr float INV_SQRT_DH = 0.20412414523193154f;
}

__device__ __forceinline__ u64 dup2f(float a) {
  u64 r; asm("mov.b64 %0, {%1, %1};" : "=l"(r) : "f"(a)); return r;
}
__device__ __forceinline__ u64 pack2f(float x, float y) {
  u64 r; asm("mov.b64 %0, {%1, %2};" : "=l"(r) : "f"(x), "f"(y)); return r;
}
__device__ __forceinline__ void fma2(u64& d, u64 a, u64 b) {
  asm("fma.rn.f32x2 %0, %1, %2, %0;" : "+l"(d) : "l"(a), "l"(b));
}
__device__ __forceinline__ float2 unpack2(u64 v) {
  float2 o; asm("mov.b64 {%0, %1}, %2;" : "=f"(o.x), "=f"(o.y) : "l"(v));
  return o;
}

// acc[4][3]: rows ty*4+r, col pairs (2tx+64j, 2tx+64j+1).
__device__ __forceinline__ void gemm_core(const float* __restrict__ sXW,
                                          const float* __restrict__ Wg,
                                          const float* __restrict__ bias,
                                          float* __restrict__ sWT,
                                          u64 acc[4][3], int tid) {
  const int ty = tid >> 5, tx = tid & 31;
#pragma unroll
  for (int j = 0; j < 3; j++) {
    float2 b = *(const float2*)(bias + 2 * tx + 64 * j);
    u64 bp = pack2f(b.x, b.y);
#pragma unroll
    for (int r = 0; r < 4; r++) acc[r][j] = bp;
  }
  float4 pf[3];
#pragma unroll
  for (int i = 0; i < 3; i++) {
    int t = tid + NT * i, kr = t / 48, cq = t - kr * 48;
    pf[i] = *(const float4*)(Wg + kr * Cc + cq * 4);
  }
  const float* arow = sXW + ty * 4 * STR;
  for (int ko = 0; ko < Cc; ko += 32) {
    __syncthreads();  // prior consumers of sWT done
#pragma unroll
    for (int i = 0; i < 3; i++) {
      int t = tid + NT * i, kr = t / 48, cq = t - kr * 48;
      *(float4*)(sWT + kr * Cc + cq * 4) = pf[i];
    }
    __syncthreads();
    if (ko + 32 < Cc) {  // prefetch next W tile under the compute below
#pragma unroll
      for (int i = 0; i < 3; i++) {
        int t = tid + NT * i, kr = t / 48, cq = t - kr * 48;
        pf[i] = *(const float4*)(Wg + (ko + 32 + kr) * Cc + cq * 4);
      }
    }
#pragma unroll
    for (int kq = 0; kq < 8; kq++) {
      float4 a4[4];
#pragma unroll
      for (int r = 0; r < 4; r++)
        a4[r] = *(const float4*)(arow + r * STR + ko + kq * 4);
#pragma unroll
      for (int kk = 0; kk < 4; kk++) {
        u64 b2[3];
#pragma unroll
        for (int j = 0; j < 3; j++)
          b2[j] = *(const u64*)(sWT + (kq * 4 + kk) * Cc + 2 * tx + 64 * j);
#pragma unroll
        for (int r = 0; r < 4; r++) {
          float av = (kk == 0) ? a4[r].x : (kk == 1) ? a4[r].y
                    : (kk == 2) ? a4[r].z : a4[r].w;
          u64 a2 = dup2f(av);
#pragma unroll
          for (int j = 0; j < 3; j++) fma2(acc[r][j], a2, b2[j]);
        }
      }
    }
  }
}

__device__ __forceinline__ void gemm_to_smem(const float* __restrict__ sXW,
                                             const float* __restrict__ Wg,
                                             const float* __restrict__ bias,
                                             float* __restrict__ sWT,
                                             float* __restrict__ dst, int tid) {
  u64 acc[4][3];
  gemm_core(sXW, Wg, bias, sWT, acc, tid);
  const int ty = tid >> 5, tx = tid & 31;
#pragma unroll
  for (int r = 0; r < 4; r++)
#pragma unroll
    for (int j = 0; j < 3; j++)
      *(float2*)(dst + (ty * 4 + r) * STR + 2 * tx + 64 * j) =
          unpack2(acc[r][j]);
  __syncthreads();
}

__device__ __forceinline__ void gemm_skip_out(const float* __restrict__ sXW,
                                              const float* __restrict__ Wg,
                                              const float* __restrict__ bias,
                                              float* __restrict__ sWT,
                                              const float* __restrict__ sAttn,
                                              float* __restrict__ out,
                                              int b, int h0, int w0, int tid) {
  u64 acc[4][3];
  gemm_core(sXW, Wg, bias, sWT, acc, tid);
  const int ty = tid >> 5, tx = tid & 31;
  const int nh = ty >> 1, nwb = (ty & 1) * 4;
#pragma unroll
  for (int j = 0; j < 3; j++) {
    const int c = 2 * tx + 64 * j;
    float lo[4], hi[4];
#pragma unroll
    for (int r = 0; r < 4; r++) {
      int g = ty * 4 + r;
      float2 v = unpack2(acc[r][j]);
      lo[r] = v.x + sAttn[g * STR + c];
      hi[r] = v.y + sAttn[g * STR + c + 1];
    }
    float* d0 = out + ((b * Cc + c) * Hc + h0 + nh) * Wc + w0 + nwb;
    *(float4*)d0 = make_float4(lo[0], lo[1], lo[2], lo[3]);
    float* d1 = out + ((b * Cc + c + 1) * Hc + h0 + nh) * Wc + w0 + nwb;
    *(float4*)d1 = make_float4(hi[0], hi[1], hi[2], hi[3]);
  }
}

__global__ void __launch_bounds__(NT, 1)
wg_kernel(const float* __restrict__ x,
          const float* __restrict__ Wq, const float* __restrict__ bq,
          const float* __restrict__ Wk, const float* __restrict__ bk,
          const float* __restrict__ Wvw, const float* __restrict__ bv,
          const float* __restrict__ Wsk, const float* __restrict__ bsk,
          float* __restrict__ out) {
  extern __shared__ float sm[];
  float* sXW = sm;
  float* sQ = sXW + XW_FLOATS;
  float* sK = sQ + XW_FLOATS;
  float* sV = sK + XW_FLOATS;
  float* sWT = sV + XW_FLOATS;   // 6144 floats; first 4096 alias Gram
  float* sG = sWT;
  float* sSq = sWT + WT_FLOATS;  // 64 floats
  int* sIdx = (int*)(sSq + NN);  // 64*9 ints

  const int tid = threadIdx.x;
  const int w = blockIdx.x;
  const int b = w / (NWH * NWW);
  const int rem = w - b * (NWH * NWW);
  const int wh = rem / NWW, ww = rem - wh * NWW;
  const int h0 = wh * WS, w0 = ww * WS;

  // ---- Phase A: gather window nodes ----
#pragma unroll
  for (int i = 0; i < 3; i++) {
    int t = tid + NT * i;          // 0..1535 : (c, nh)
    int c = t >> 3, nh = t & 7;
    const float* src = x + ((b * Cc + c) * Hc + h0 + nh) * Wc + w0;
    float4 v0 = *(const float4*)src;
    float4 v1 = *(const float4*)(src + 4);
    float* d = sXW + (nh * 8) * STR + c;
    d[0 * STR] = v0.x; d[1 * STR] = v0.y; d[2 * STR] = v0.z; d[3 * STR] = v0.w;
    d[4 * STR] = v1.x; d[5 * STR] = v1.y; d[6 * STR] = v1.z; d[7 * STR] = v1.w;
  }
  __syncthreads();

  // ---- Phase B1: Gram matrix, 256 threads, 4x4 spread tiles, k-pair fma2.
  // rows {tn+16i}, cols {tm+16j}: conflict-free LDS.128 (lane stride 784B).
  if (tid < 256) {
    const int tn = tid >> 4, tm = tid & 15;
    u64 acc2[4][4] = {};
#pragma unroll 2
    for (int k = 0; k < Cc; k += 4) {
      ulonglong2 a[4], bb[4];
#pragma unroll
      for (int i = 0; i < 4; i++)
        a[i] = *(const ulonglong2*)(sXW + (tn + 16 * i) * STR + k);
#pragma unroll
      for (int j = 0; j < 4; j++)
        bb[j] = *(const ulonglong2*)(sXW + (tm + 16 * j) * STR + k);
#pragma unroll
      for (int i = 0; i < 4; i++)
#pragma unroll
        for (int j = 0; j < 4; j++) {
          fma2(acc2[i][j], a[i].x, bb[j].x);
          fma2(acc2[i][j], a[i].y, bb[j].y);
        }
    }
#pragma unroll
    for (int i = 0; i < 4; i++)
#pragma unroll
      for (int j = 0; j < 4; j++) {
        float2 v = unpack2(acc2[i][j]);
        sG[(tn + 16 * i) * NN + tm + 16 * j] = v.x + v.y;
      }
  }
  __syncthreads();
  if (tid < NN) sSq[tid] = sG[tid * (NN + 1)];
  __syncthreads();

  // ---- Phase B2: top-9 nearest neighbors (stable, exact fp32) ----
  if (tid < NN) {
    const int n = tid;
    unsigned long long mask = 1ull << n;  // exclude self
    const float sqn = sSq[n];
    const float* grow = sG + n * NN;
#pragma unroll 1
    for (int kk = 0; kk < KK; kk++) {
      float best = 3.0e38f;
      int bi = 0;
#pragma unroll 4
      for (int m = 0; m < NN; m++) {
        float d = sqn + sSq[m] - 2.0f * grow[m];
        if ((mask >> m) & 1ull) d = 3.9e38f;
        if (d < best) { best = d; bi = m; }  // '<' = lowest index wins ties
      }
      mask |= 1ull << bi;
      sIdx[n * KK + kk] = bi;
    }
  }
  __syncthreads();

  // ---- Phase C: Q, K, V projections (f32x2) ----
  gemm_to_smem(sXW, Wq, bq, sWT, sQ, tid);
  gemm_to_smem(sXW, Wk, bk, sWT, sK, tid);
  gemm_to_smem(sXW, Wvw, bv, sWT, sV, tid);

  // ---- Phase D: 9-neighbor softmax attention; 512 thr = one (n,h) each ----
  {
    const int n = tid & (NN - 1);
    const int h = tid >> 6;
    const float* qp = sQ + n * STR + h * DH;
    float q[DH];
#pragma unroll
    for (int d4 = 0; d4 < DH / 4; d4++) {
      float4 v = *(const float4*)(qp + d4 * 4);
      q[d4 * 4 + 0] = v.x; q[d4 * 4 + 1] = v.y;
      q[d4 * 4 + 2] = v.z; q[d4 * 4 + 3] = v.w;
    }
    float sc[KK];
    int nb[KK];
#pragma unroll
    for (int kk = 0; kk < KK; kk++) {
      int m = sIdx[n * KK + kk];
      nb[kk] = m;
      const float* kp = sK + m * STR + h * DH;
      float s = 0.0f;
#pragma unroll
      for (int d4 = 0; d4 < DH / 4; d4++) {
        float4 v = *(const float4*)(kp + d4 * 4);
        s = fmaf(q[d4 * 4 + 0], v.x, s);
        s = fmaf(q[d4 * 4 + 1], v.y, s);
        s = fmaf(q[d4 * 4 + 2], v.z, s);
        s = fmaf(q[d4 * 4 + 3], v.w, s);
      }
      sc[kk] = s * INV_SQRT_DH;
    }
    float mx = sc[0];
#pragma unroll
    for (int kk = 1; kk < KK; kk++) mx = fmaxf(mx, sc[kk]);
    float ssum = 0.0f;
#pragma unroll
    for (int kk = 0; kk < KK; kk++) { sc[kk] = __expf(sc[kk] - mx); ssum += sc[kk]; }
    const float inv = 1.0f / ssum;
    float o[DH] = {};
#pragma unroll
    for (int kk = 0; kk < KK; kk++) {
      float a = sc[kk] * inv;
      const float* vp = sV + nb[kk] * STR + h * DH;
#pragma unroll
      for (int d4 = 0; d4 < DH / 4; d4++) {
        float4 v = *(const float4*)(vp + d4 * 4);
        o[d4 * 4 + 0] = fmaf(a, v.x, o[d4 * 4 + 0]);
        o[d4 * 4 + 1] = fmaf(a, v.y, o[d4 * 4 + 1]);
        o[d4 * 4 + 2] = fmaf(a, v.z, o[d4 * 4 + 2]);
        o[d4 * 4 + 3] = fmaf(a, v.w, o[d4 * 4 + 3]);
      }
    }
    float* op = sQ + n * STR + h * DH;  // attn out overwrites own q segment
#pragma unroll
    for (int d4 = 0; d4 < DH / 4; d4++)
      *(float4*)(op + d4 * 4) =
          make_float4(o[d4 * 4 + 0], o[d4 * 4 + 1], o[d4 * 4 + 2], o[d4 * 4 + 3]);
  }
  // first __syncthreads inside gemm_skip_out guards sQ reads

  // ---- Phase E: skip GEMM + attn add + scatter to [B,C,H,W] ----
  gemm_skip_out(sXW, Wsk, bsk, sWT, sQ, out, b, h0, w0, tid);
}

extern "C" void kernel_launch(void* const* d_in, const int* in_sizes, int n_in,
                              void* d_out, int out_size) {
  const float* x   = (const float*)d_in[0];
  const float* Wq  = (const float*)d_in[1];
  const float* bq  = (const float*)d_in[2];
  const float* Wk  = (const float*)d_in[3];
  const float* bk  = (const float*)d_in[4];
  const float* Wv  = (const float*)d_in[5];
  const float* bv  = (const float*)d_in[6];
  const float* Wsk = (const float*)d_in[7];
  const float* bsk = (const float*)d_in[8];
  float* out = (float*)d_out;

  cudaFuncSetAttribute(wg_kernel, cudaFuncAttributeMaxDynamicSharedMemorySize,
                       (int)SMEM_BYTES);
  wg_kernel<<<WB, NT, SMEM_BYTES>>>(x, Wq, bq, Wk, bk, Wv, bv, Wsk, bsk, out);
}